// round 11
// baseline (speedup 1.0000x reference)
#include <cuda_runtime.h>
#include <cuda_bf16.h>

// ---------------------------------------------------------------------------
// G2EquivariantFeedForward, GB300 sm_103a — round 11
//
// Closed form: upd = a*x + b*x^2 + c*x^3 = (P, Q*v) for x = r + v,
//   P = a*r + b*(r^2-n^2) + c*r*(r^2-3n^2)
//   Q = a + 2*b*r + c*(3r^2-n^2),  n^2=|v|^2,  |upd|^2 = P^2 + Q^2 n^2
//
// Round 11 = round 8 (best: NS=2 f32x2 streams, constant-port weights,
// 57.8us) + occupancy: #pragma unroll 2 on the MLP loop (shallower LDC
// software-pipelining -> fewer live regs) and __launch_bounds__(128,10)
// (51-reg target -> 10 blocks/SM = 62% occupancy vs 46%). Round-9/10
// established NS=2 as the instruction-count sweet spot and that the fma
// pipe (fixed ~35us busy) is fed by warp count, not per-thread ILP.
// ---------------------------------------------------------------------------

typedef unsigned long long U64;

__device__ __forceinline__ U64 pk2(float lo, float hi) {
    U64 r; asm("mov.b64 %0, {%1, %2};" : "=l"(r) : "f"(lo), "f"(hi)); return r;
}
__device__ __forceinline__ void upk2(U64 v, float& lo, float& hi) {
    asm("mov.b64 {%0, %1}, %2;" : "=f"(lo), "=f"(hi) : "l"(v));
}
__device__ __forceinline__ U64 fma2(U64 a, U64 b, U64 c) {
    U64 d; asm("fma.rn.f32x2 %0, %1, %2, %3;" : "=l"(d) : "l"(a), "l"(b), "l"(c)); return d;
}
__device__ __forceinline__ U64 mul2(U64 a, U64 b) {
    U64 d; asm("mul.rn.f32x2 %0, %1, %2;" : "=l"(d) : "l"(a), "l"(b)); return d;
}
__device__ __forceinline__ U64 add2(U64 a, U64 b) {
    U64 d; asm("add.rn.f32x2 %0, %1, %2;" : "=l"(d) : "l"(a), "l"(b)); return d;
}
__device__ __forceinline__ float tanh_ap(float x) {
    float t; asm("tanh.approx.f32 %0, %1;" : "=f"(t) : "f"(x)); return t;
}
__device__ __forceinline__ float sqrt_ap(float x) {
    float t; asm("sqrt.approx.f32 %0, %1;" : "=f"(t) : "f"(x)); return t;
}
__device__ __forceinline__ float rsqrt_ap(float x) {
    float t; asm("rsqrt.approx.f32 %0, %1;" : "=f"(t) : "f"(x)); return t;
}

__device__ __forceinline__ float norm2_imag(const float4& a0, const float4& a1) {
    float n = a0.y * a0.y;
    n = fmaf(a0.z, a0.z, n);
    n = fmaf(a0.w, a0.w, n);
    n = fmaf(a1.x, a1.x, n);
    n = fmaf(a1.y, a1.y, n);
    n = fmaf(a1.z, a1.z, n);
    n = fmaf(a1.w, a1.w, n);
    return n;
}

// ---- packed weight tables: built on device, then copied into __constant__ ----
struct __align__(16) CTab {
    ulonglong2 W1[32];   // (w0,w0 | w1,w1)
    ulonglong2 BW[32];   // (b1,b1 | 0.5*w2c,0.5*w2c)
    ulonglong2 W2[32];   // (0.5*w2a,.. | 0.5*w2b,..)
    U64        B2[3];    // (b2k, b2k)
    float      scal[2];  // lam, 1-lam
};

__device__   CTab dScratch;   // written by prep kernel
__constant__ CTab cT;         // read by main kernel (constant port)

__global__ void prep_kernel(const float* __restrict__ W1,
                            const float* __restrict__ b1,
                            const float* __restrict__ W2,
                            const float* __restrict__ b2,
                            const float* __restrict__ alpha)
{
    const int t = threadIdx.x;     // 32 threads
    float w0 = W1[2 * t], w1 = W1[2 * t + 1];
    ulonglong2 q; q.x = pk2(w0, w0); q.y = pk2(w1, w1);
    dScratch.W1[t] = q;
    float bb = b1[t], wc = 0.5f * W2[64 + t];
    ulonglong2 qb; qb.x = pk2(bb, bb); qb.y = pk2(wc, wc);
    dScratch.BW[t] = qb;
    float wa = 0.5f * W2[t], wb = 0.5f * W2[32 + t];
    ulonglong2 q2; q2.x = pk2(wa, wa); q2.y = pk2(wb, wb);
    dScratch.W2[t] = q2;
    if (t == 0) {
        float al  = alpha[0];
        float lam = 1.0f / (1.0f + __expf(-al));
        dScratch.scal[0] = lam;
        dScratch.scal[1] = 1.0f - lam;
        dScratch.B2[0] = pk2(b2[0], b2[0]);
        dScratch.B2[1] = pk2(b2[1], b2[1]);
        dScratch.B2[2] = pk2(b2[2], b2[2]);
    }
}

#define TPB 128          // threads per block
#define OPB 512          // octonions per block (4 per thread)

__global__ __launch_bounds__(TPB, 10)
void g2ff_kernel(const float4* __restrict__ in4,
                 float4*       __restrict__ out4)
{
    const int t = threadIdx.x;
    const int base = blockIdx.x * OPB;
    const int mA = base + t;
    const int mB = base + TPB + t;
    const int mC = base + 2 * TPB + t;
    const int mD = base + 3 * TPB + t;

    // ---- prologue: scalar n^2 per octonion; pack only (r, np) pairs ----
    U64 Xp0, Xnp, Yp0, Ynp;
    {
        float4 a0 = in4[2 * mA + 0];
        float4 a1 = in4[2 * mA + 1];
        float4 b0 = in4[2 * mB + 0];
        float4 b1v = in4[2 * mB + 1];
        float nA = norm2_imag(a0, a1);
        float nB = norm2_imag(b0, b1v);
        Xp0 = pk2(a0.x, b0.x);
        Xnp = pk2(sqrt_ap(nA), sqrt_ap(nB));
    }
    {
        float4 a0 = in4[2 * mC + 0];
        float4 a1 = in4[2 * mC + 1];
        float4 b0 = in4[2 * mD + 0];
        float4 b1v = in4[2 * mD + 1];
        float nA = norm2_imag(a0, a1);
        float nB = norm2_imag(b0, b1v);
        Yp0 = pk2(a0.x, b0.x);
        Ynp = pk2(sqrt_ap(nA), sqrt_ap(nB));
    }

    // GELU-tanh constants
    const U64 C1 = pk2(0.7978845608028654f, 0.7978845608028654f);
    const U64 C2 = pk2(0.035677408136300125f, 0.035677408136300125f);

    U64 aAX = cT.B2[0], aBX = cT.B2[1], aCX = cT.B2[2];
    U64 aAY = cT.B2[0], aBY = cT.B2[1], aCY = cT.B2[2];

#pragma unroll 2
    for (int j = 0; j < 32; j++) {
        ulonglong2 w1j = cT.W1[j];   // LDC.128 (constant port, off L1tex)
        ulonglong2 bwj = cT.BW[j];
        ulonglong2 w2j = cT.W2[j];

        // stream X:  h' = z*(1+tanh(u)) = 2*gelu(z); W2 tables pre-halved
        {
            U64 z  = fma2(Xnp, w1j.y, fma2(Xp0, w1j.x, bwj.x));
            U64 z2 = mul2(z, z);
            U64 qq = fma2(z2, C2, C1);
            U64 u  = mul2(z, qq);
            float ul, uh; upk2(u, ul, uh);
            U64 tt = pk2(tanh_ap(ul), tanh_ap(uh));
            U64 h  = fma2(z, tt, z);
            aAX = fma2(h, w2j.x, aAX);
            aBX = fma2(h, w2j.y, aBX);
            aCX = fma2(h, bwj.y, aCX);
        }
        // stream Y
        {
            U64 z  = fma2(Ynp, w1j.y, fma2(Yp0, w1j.x, bwj.x));
            U64 z2 = mul2(z, z);
            U64 qq = fma2(z2, C2, C1);
            U64 u  = mul2(z, qq);
            float ul, uh; upk2(u, ul, uh);
            U64 tt = pk2(tanh_ap(ul), tanh_ap(uh));
            U64 h  = fma2(z, tt, z);
            aAY = fma2(h, w2j.x, aAY);
            aBY = fma2(h, w2j.y, aBY);
            aCY = fma2(h, bwj.y, aCY);
        }
    }

    const U64 N1  = pk2(-1.0f, -1.0f);
    const U64 N3  = pk2(-3.0f, -3.0f);
    const U64 TWO = pk2(2.0f, 2.0f);

    const float lam = cT.scal[0], oml = cT.scal[1];
    const U64 LAM = pk2(lam, lam);
    const U64 OML = pk2(oml, oml);

    // ---- epilogue stream X (re-load octonions from global; L2 hit) ----
    {
        U64 n2 = mul2(Xnp, Xnp);              // recompute (np = sqrt(n2))
        U64 r2 = mul2(Xp0, Xp0);
        U64 s2 = fma2(n2, N1, r2);            // r^2 - n^2
        U64 u3 = fma2(n2, N3, r2);            // r^2 - 3n^2
        U64 s3 = mul2(Xp0, u3);
        U64 t3 = fma2(r2, TWO, s2);           // 3r^2 - n^2
        U64 P  = fma2(aAX, Xp0, fma2(aBX, s2, mul2(aCX, s3)));
        U64 tr = add2(Xp0, Xp0);
        U64 Q  = fma2(aCX, t3, fma2(aBX, tr, aAX));
        U64 ss = fma2(mul2(Q, Q), n2, mul2(P, P));
        float sl, sh; upk2(ss, sl, sh);
        sl = fmaxf(sl, 1e-16f);
        sh = fmaxf(sh, 1e-16f);
        U64 inv = pk2(rsqrt_ap(sl), rsqrt_ap(sh));
        U64 li  = mul2(LAM, inv);
        U64 K   = fma2(li, Q, OML);
        U64 o0  = fma2(li, P, mul2(Xp0, OML));

        float Klo, Khi; upk2(K, Klo, Khi);
        float olo, ohi; upk2(o0, olo, ohi);

        float4 a0 = in4[2 * mA + 0];
        float4 a1 = in4[2 * mA + 1];
        a0.x = olo;
        a0.y *= Klo; a0.z *= Klo; a0.w *= Klo;
        a1.x *= Klo; a1.y *= Klo; a1.z *= Klo; a1.w *= Klo;
        out4[2 * mA + 0] = a0;
        out4[2 * mA + 1] = a1;

        float4 b0 = in4[2 * mB + 0];
        float4 b1v = in4[2 * mB + 1];
        b0.x = ohi;
        b0.y *= Khi; b0.z *= Khi; b0.w *= Khi;
        b1v.x *= Khi; b1v.y *= Khi; b1v.z *= Khi; b1v.w *= Khi;
        out4[2 * mB + 0] = b0;
        out4[2 * mB + 1] = b1v;
    }
    // ---- epilogue stream Y ----
    {
        U64 n2 = mul2(Ynp, Ynp);
        U64 r2 = mul2(Yp0, Yp0);
        U64 s2 = fma2(n2, N1, r2);
        U64 u3 = fma2(n2, N3, r2);
        U64 s3 = mul2(Yp0, u3);
        U64 t3 = fma2(r2, TWO, s2);
        U64 P  = fma2(aAY, Yp0, fma2(aBY, s2, mul2(aCY, s3)));
        U64 tr = add2(Yp0, Yp0);
        U64 Q  = fma2(aCY, t3, fma2(aBY, tr, aAY));
        U64 ss = fma2(mul2(Q, Q), n2, mul2(P, P));
        float sl, sh; upk2(ss, sl, sh);
        sl = fmaxf(sl, 1e-16f);
        sh = fmaxf(sh, 1e-16f);
        U64 inv = pk2(rsqrt_ap(sl), rsqrt_ap(sh));
        U64 li  = mul2(LAM, inv);
        U64 K   = fma2(li, Q, OML);
        U64 o0  = fma2(li, P, mul2(Yp0, OML));

        float Klo, Khi; upk2(K, Klo, Khi);
        float olo, ohi; upk2(o0, olo, ohi);

        float4 a0 = in4[2 * mC + 0];
        float4 a1 = in4[2 * mC + 1];
        a0.x = olo;
        a0.y *= Klo; a0.z *= Klo; a0.w *= Klo;
        a1.x *= Klo; a1.y *= Klo; a1.z *= Klo; a1.w *= Klo;
        out4[2 * mC + 0] = a0;
        out4[2 * mC + 1] = a1;

        float4 b0 = in4[2 * mD + 0];
        float4 b1v = in4[2 * mD + 1];
        b0.x = ohi;
        b0.y *= Khi; b0.z *= Khi; b0.w *= Khi;
        b1v.x *= Khi; b1v.y *= Khi; b1v.z *= Khi; b1v.w *= Khi;
        out4[2 * mD + 0] = b0;
        out4[2 * mD + 1] = b1v;
    }
}

extern "C" void kernel_launch(void* const* d_in, const int* in_sizes, int n_in,
                              void* d_out, int out_size)
{
    const float* o     = (const float*)d_in[0];
    const float* W1    = (const float*)d_in[1];
    const float* b1    = (const float*)d_in[2];
    const float* W2    = (const float*)d_in[3];
    const float* b2    = (const float*)d_in[4];
    const float* alpha = (const float*)d_in[5];

    // 1) pack weight tables on device
    prep_kernel<<<1, 32>>>(W1, b1, W2, b2, alpha);

    // 2) copy packed tables into __constant__ (D2D memcpy node, capturable)
    void* scratch_addr = nullptr;
    cudaGetSymbolAddress(&scratch_addr, dScratch);
    cudaMemcpyToSymbolAsync(cT, scratch_addr, sizeof(CTab), 0,
                            cudaMemcpyDeviceToDevice);

    // 3) main kernel
    const int total = in_sizes[0];          // 33,554,432 floats
    const int octs  = total / 8;            // 4,194,304 octonions
    const int blocks = octs / OPB;          // 8192

    g2ff_kernel<<<blocks, TPB>>>((const float4*)o, (float4*)d_out);
}

// round 12
// speedup vs baseline: 1.0665x; 1.0665x over previous
#include <cuda_runtime.h>
#include <cuda_bf16.h>

// ---------------------------------------------------------------------------
// G2EquivariantFeedForward, GB300 sm_103a — round 12
//
// Closed form: upd = a*x + b*x^2 + c*x^3 = (P, Q*v) for x = r + v,
//   P = a*r + b*(r^2-n^2) + c*r*(r^2-3n^2)
//   Q = a + 2*b*r + c*(3r^2-n^2),  n^2=|v|^2,  |upd|^2 = P^2 + Q^2 n^2
//
// Round 12 = round 8 (best main kernel: NS=2 f32x2 streams, constant-port
// weights) with #pragma unroll 4 + __launch_bounds__(128,9):
//   - unroll 4 keeps loop overhead at 1/4 of round 11's unroll-2 attempt
//     while shrinking the LDC prefetch window -> natural regs ~54-56
//   - 9 blocks/SM (56-reg cap) -> ~56% occupancy vs round 8's 46%
// Round 9/10/11 mapped the frontier: NS=2 is slot-minimal; occupancy must
// come without adding instructions or spills.
// ---------------------------------------------------------------------------

typedef unsigned long long U64;

__device__ __forceinline__ U64 pk2(float lo, float hi) {
    U64 r; asm("mov.b64 %0, {%1, %2};" : "=l"(r) : "f"(lo), "f"(hi)); return r;
}
__device__ __forceinline__ void upk2(U64 v, float& lo, float& hi) {
    asm("mov.b64 {%0, %1}, %2;" : "=f"(lo), "=f"(hi) : "l"(v));
}
__device__ __forceinline__ U64 fma2(U64 a, U64 b, U64 c) {
    U64 d; asm("fma.rn.f32x2 %0, %1, %2, %3;" : "=l"(d) : "l"(a), "l"(b), "l"(c)); return d;
}
__device__ __forceinline__ U64 mul2(U64 a, U64 b) {
    U64 d; asm("mul.rn.f32x2 %0, %1, %2;" : "=l"(d) : "l"(a), "l"(b)); return d;
}
__device__ __forceinline__ U64 add2(U64 a, U64 b) {
    U64 d; asm("add.rn.f32x2 %0, %1, %2;" : "=l"(d) : "l"(a), "l"(b)); return d;
}
__device__ __forceinline__ float tanh_ap(float x) {
    float t; asm("tanh.approx.f32 %0, %1;" : "=f"(t) : "f"(x)); return t;
}
__device__ __forceinline__ float sqrt_ap(float x) {
    float t; asm("sqrt.approx.f32 %0, %1;" : "=f"(t) : "f"(x)); return t;
}
__device__ __forceinline__ float rsqrt_ap(float x) {
    float t; asm("rsqrt.approx.f32 %0, %1;" : "=f"(t) : "f"(x)); return t;
}

__device__ __forceinline__ float norm2_imag(const float4& a0, const float4& a1) {
    float n = a0.y * a0.y;
    n = fmaf(a0.z, a0.z, n);
    n = fmaf(a0.w, a0.w, n);
    n = fmaf(a1.x, a1.x, n);
    n = fmaf(a1.y, a1.y, n);
    n = fmaf(a1.z, a1.z, n);
    n = fmaf(a1.w, a1.w, n);
    return n;
}

// ---- packed weight tables: built on device, then copied into __constant__ ----
struct __align__(16) CTab {
    ulonglong2 W1[32];   // (w0,w0 | w1,w1)
    ulonglong2 BW[32];   // (b1,b1 | 0.5*w2c,0.5*w2c)
    ulonglong2 W2[32];   // (0.5*w2a,.. | 0.5*w2b,..)
    U64        B2[3];    // (b2k, b2k)
    float      scal[2];  // lam, 1-lam
};

__device__   CTab dScratch;   // written by prep kernel
__constant__ CTab cT;         // read by main kernel (constant port)

__global__ void prep_kernel(const float* __restrict__ W1,
                            const float* __restrict__ b1,
                            const float* __restrict__ W2,
                            const float* __restrict__ b2,
                            const float* __restrict__ alpha)
{
    const int t = threadIdx.x;     // 32 threads
    float w0 = W1[2 * t], w1 = W1[2 * t + 1];
    ulonglong2 q; q.x = pk2(w0, w0); q.y = pk2(w1, w1);
    dScratch.W1[t] = q;
    float bb = b1[t], wc = 0.5f * W2[64 + t];
    ulonglong2 qb; qb.x = pk2(bb, bb); qb.y = pk2(wc, wc);
    dScratch.BW[t] = qb;
    float wa = 0.5f * W2[t], wb = 0.5f * W2[32 + t];
    ulonglong2 q2; q2.x = pk2(wa, wa); q2.y = pk2(wb, wb);
    dScratch.W2[t] = q2;
    if (t == 0) {
        float al  = alpha[0];
        float lam = 1.0f / (1.0f + __expf(-al));
        dScratch.scal[0] = lam;
        dScratch.scal[1] = 1.0f - lam;
        dScratch.B2[0] = pk2(b2[0], b2[0]);
        dScratch.B2[1] = pk2(b2[1], b2[1]);
        dScratch.B2[2] = pk2(b2[2], b2[2]);
    }
}

#define TPB 128          // threads per block
#define OPB 512          // octonions per block (4 per thread)

__global__ __launch_bounds__(TPB, 9)
void g2ff_kernel(const float4* __restrict__ in4,
                 float4*       __restrict__ out4)
{
    const int t = threadIdx.x;
    const int base = blockIdx.x * OPB;
    const int mA = base + t;
    const int mB = base + TPB + t;
    const int mC = base + 2 * TPB + t;
    const int mD = base + 3 * TPB + t;

    // ---- prologue: scalar n^2 per octonion; pack only (r, np) pairs ----
    U64 Xp0, Xnp, Yp0, Ynp;
    {
        float4 a0 = in4[2 * mA + 0];
        float4 a1 = in4[2 * mA + 1];
        float4 b0 = in4[2 * mB + 0];
        float4 b1v = in4[2 * mB + 1];
        float nA = norm2_imag(a0, a1);
        float nB = norm2_imag(b0, b1v);
        Xp0 = pk2(a0.x, b0.x);
        Xnp = pk2(sqrt_ap(nA), sqrt_ap(nB));
    }
    {
        float4 a0 = in4[2 * mC + 0];
        float4 a1 = in4[2 * mC + 1];
        float4 b0 = in4[2 * mD + 0];
        float4 b1v = in4[2 * mD + 1];
        float nA = norm2_imag(a0, a1);
        float nB = norm2_imag(b0, b1v);
        Yp0 = pk2(a0.x, b0.x);
        Ynp = pk2(sqrt_ap(nA), sqrt_ap(nB));
    }

    // GELU-tanh constants
    const U64 C1 = pk2(0.7978845608028654f, 0.7978845608028654f);
    const U64 C2 = pk2(0.035677408136300125f, 0.035677408136300125f);

    U64 aAX = cT.B2[0], aBX = cT.B2[1], aCX = cT.B2[2];
    U64 aAY = cT.B2[0], aBY = cT.B2[1], aCY = cT.B2[2];

#pragma unroll 4
    for (int j = 0; j < 32; j++) {
        ulonglong2 w1j = cT.W1[j];   // LDC.128 (constant port, off L1tex)
        ulonglong2 bwj = cT.BW[j];
        ulonglong2 w2j = cT.W2[j];

        // stream X:  h' = z*(1+tanh(u)) = 2*gelu(z); W2 tables pre-halved
        {
            U64 z  = fma2(Xnp, w1j.y, fma2(Xp0, w1j.x, bwj.x));
            U64 z2 = mul2(z, z);
            U64 qq = fma2(z2, C2, C1);
            U64 u  = mul2(z, qq);
            float ul, uh; upk2(u, ul, uh);
            U64 tt = pk2(tanh_ap(ul), tanh_ap(uh));
            U64 h  = fma2(z, tt, z);
            aAX = fma2(h, w2j.x, aAX);
            aBX = fma2(h, w2j.y, aBX);
            aCX = fma2(h, bwj.y, aCX);
        }
        // stream Y
        {
            U64 z  = fma2(Ynp, w1j.y, fma2(Yp0, w1j.x, bwj.x));
            U64 z2 = mul2(z, z);
            U64 qq = fma2(z2, C2, C1);
            U64 u  = mul2(z, qq);
            float ul, uh; upk2(u, ul, uh);
            U64 tt = pk2(tanh_ap(ul), tanh_ap(uh));
            U64 h  = fma2(z, tt, z);
            aAY = fma2(h, w2j.x, aAY);
            aBY = fma2(h, w2j.y, aBY);
            aCY = fma2(h, bwj.y, aCY);
        }
    }

    const U64 N1  = pk2(-1.0f, -1.0f);
    const U64 N3  = pk2(-3.0f, -3.0f);
    const U64 TWO = pk2(2.0f, 2.0f);

    const float lam = cT.scal[0], oml = cT.scal[1];
    const U64 LAM = pk2(lam, lam);
    const U64 OML = pk2(oml, oml);

    // ---- epilogue stream X (re-load octonions from global; L2 hit) ----
    {
        U64 n2 = mul2(Xnp, Xnp);              // recompute (np = sqrt(n2))
        U64 r2 = mul2(Xp0, Xp0);
        U64 s2 = fma2(n2, N1, r2);            // r^2 - n^2
        U64 u3 = fma2(n2, N3, r2);            // r^2 - 3n^2
        U64 s3 = mul2(Xp0, u3);
        U64 t3 = fma2(r2, TWO, s2);           // 3r^2 - n^2
        U64 P  = fma2(aAX, Xp0, fma2(aBX, s2, mul2(aCX, s3)));
        U64 tr = add2(Xp0, Xp0);
        U64 Q  = fma2(aCX, t3, fma2(aBX, tr, aAX));
        U64 ss = fma2(mul2(Q, Q), n2, mul2(P, P));
        float sl, sh; upk2(ss, sl, sh);
        sl = fmaxf(sl, 1e-16f);
        sh = fmaxf(sh, 1e-16f);
        U64 inv = pk2(rsqrt_ap(sl), rsqrt_ap(sh));
        U64 li  = mul2(LAM, inv);
        U64 K   = fma2(li, Q, OML);
        U64 o0  = fma2(li, P, mul2(Xp0, OML));

        float Klo, Khi; upk2(K, Klo, Khi);
        float olo, ohi; upk2(o0, olo, ohi);

        float4 a0 = in4[2 * mA + 0];
        float4 a1 = in4[2 * mA + 1];
        a0.x = olo;
        a0.y *= Klo; a0.z *= Klo; a0.w *= Klo;
        a1.x *= Klo; a1.y *= Klo; a1.z *= Klo; a1.w *= Klo;
        out4[2 * mA + 0] = a0;
        out4[2 * mA + 1] = a1;

        float4 b0 = in4[2 * mB + 0];
        float4 b1v = in4[2 * mB + 1];
        b0.x = ohi;
        b0.y *= Khi; b0.z *= Khi; b0.w *= Khi;
        b1v.x *= Khi; b1v.y *= Khi; b1v.z *= Khi; b1v.w *= Khi;
        out4[2 * mB + 0] = b0;
        out4[2 * mB + 1] = b1v;
    }
    // ---- epilogue stream Y ----
    {
        U64 n2 = mul2(Ynp, Ynp);
        U64 r2 = mul2(Yp0, Yp0);
        U64 s2 = fma2(n2, N1, r2);
        U64 u3 = fma2(n2, N3, r2);
        U64 s3 = mul2(Yp0, u3);
        U64 t3 = fma2(r2, TWO, s2);
        U64 P  = fma2(aAY, Yp0, fma2(aBY, s2, mul2(aCY, s3)));
        U64 tr = add2(Yp0, Yp0);
        U64 Q  = fma2(aCY, t3, fma2(aBY, tr, aAY));
        U64 ss = fma2(mul2(Q, Q), n2, mul2(P, P));
        float sl, sh; upk2(ss, sl, sh);
        sl = fmaxf(sl, 1e-16f);
        sh = fmaxf(sh, 1e-16f);
        U64 inv = pk2(rsqrt_ap(sl), rsqrt_ap(sh));
        U64 li  = mul2(LAM, inv);
        U64 K   = fma2(li, Q, OML);
        U64 o0  = fma2(li, P, mul2(Yp0, OML));

        float Klo, Khi; upk2(K, Klo, Khi);
        float olo, ohi; upk2(o0, olo, ohi);

        float4 a0 = in4[2 * mC + 0];
        float4 a1 = in4[2 * mC + 1];
        a0.x = olo;
        a0.y *= Klo; a0.z *= Klo; a0.w *= Klo;
        a1.x *= Klo; a1.y *= Klo; a1.z *= Klo; a1.w *= Klo;
        out4[2 * mC + 0] = a0;
        out4[2 * mC + 1] = a1;

        float4 b0 = in4[2 * mD + 0];
        float4 b1v = in4[2 * mD + 1];
        b0.x = ohi;
        b0.y *= Khi; b0.z *= Khi; b0.w *= Khi;
        b1v.x *= Khi; b1v.y *= Khi; b1v.z *= Khi; b1v.w *= Khi;
        out4[2 * mD + 0] = b0;
        out4[2 * mD + 1] = b1v;
    }
}

extern "C" void kernel_launch(void* const* d_in, const int* in_sizes, int n_in,
                              void* d_out, int out_size)
{
    const float* o     = (const float*)d_in[0];
    const float* W1    = (const float*)d_in[1];
    const float* b1    = (const float*)d_in[2];
    const float* W2    = (const float*)d_in[3];
    const float* b2    = (const float*)d_in[4];
    const float* alpha = (const float*)d_in[5];

    // 1) pack weight tables on device
    prep_kernel<<<1, 32>>>(W1, b1, W2, b2, alpha);

    // 2) copy packed tables into __constant__ (D2D memcpy node, capturable)
    void* scratch_addr = nullptr;
    cudaGetSymbolAddress(&scratch_addr, dScratch);
    cudaMemcpyToSymbolAsync(cT, scratch_addr, sizeof(CTab), 0,
                            cudaMemcpyDeviceToDevice);

    // 3) main kernel
    const int total = in_sizes[0];          // 33,554,432 floats
    const int octs  = total / 8;            // 4,194,304 octonions
    const int blocks = octs / OPB;          // 8192

    g2ff_kernel<<<blocks, TPB>>>((const float4*)o, (float4*)d_out);
}

// round 13
// speedup vs baseline: 1.0791x; 1.0118x over previous
#include <cuda_runtime.h>
#include <cuda_bf16.h>

// ---------------------------------------------------------------------------
// G2EquivariantFeedForward, GB300 sm_103a — round 13
//
// Closed form: upd = a*x + b*x^2 + c*x^3 = (P, Q*v) for x = r + v,
//   P = a*r + b*(r^2-n^2) + c*r*(r^2-3n^2)
//   Q = a + 2*b*r + c*(3r^2-n^2),  n^2=|v|^2,  |upd|^2 = P^2 + Q^2 n^2
//
// Round 13 = round 8 byte-identical (best total 57.8us: NS=2 f32x2 streams,
// FULL unroll, constant-port weights) + __launch_bounds__(128,9) only.
// Rounds 11/12 showed partial unroll grows issued slots and cancels the
// occupancy win; here the full-unroll schedule (32.7us-equiv slots) is kept
// and ptxas only has to shave 5 regs (61->56), which it can do by
// rematerializing the ~14 regs of splat constants. 9 blocks/SM -> ~51% occ.
// ---------------------------------------------------------------------------

typedef unsigned long long U64;

__device__ __forceinline__ U64 pk2(float lo, float hi) {
    U64 r; asm("mov.b64 %0, {%1, %2};" : "=l"(r) : "f"(lo), "f"(hi)); return r;
}
__device__ __forceinline__ void upk2(U64 v, float& lo, float& hi) {
    asm("mov.b64 {%0, %1}, %2;" : "=f"(lo), "=f"(hi) : "l"(v));
}
__device__ __forceinline__ U64 fma2(U64 a, U64 b, U64 c) {
    U64 d; asm("fma.rn.f32x2 %0, %1, %2, %3;" : "=l"(d) : "l"(a), "l"(b), "l"(c)); return d;
}
__device__ __forceinline__ U64 mul2(U64 a, U64 b) {
    U64 d; asm("mul.rn.f32x2 %0, %1, %2;" : "=l"(d) : "l"(a), "l"(b)); return d;
}
__device__ __forceinline__ U64 add2(U64 a, U64 b) {
    U64 d; asm("add.rn.f32x2 %0, %1, %2;" : "=l"(d) : "l"(a), "l"(b)); return d;
}
__device__ __forceinline__ float tanh_ap(float x) {
    float t; asm("tanh.approx.f32 %0, %1;" : "=f"(t) : "f"(x)); return t;
}
__device__ __forceinline__ float sqrt_ap(float x) {
    float t; asm("sqrt.approx.f32 %0, %1;" : "=f"(t) : "f"(x)); return t;
}
__device__ __forceinline__ float rsqrt_ap(float x) {
    float t; asm("rsqrt.approx.f32 %0, %1;" : "=f"(t) : "f"(x)); return t;
}

__device__ __forceinline__ float norm2_imag(const float4& a0, const float4& a1) {
    float n = a0.y * a0.y;
    n = fmaf(a0.z, a0.z, n);
    n = fmaf(a0.w, a0.w, n);
    n = fmaf(a1.x, a1.x, n);
    n = fmaf(a1.y, a1.y, n);
    n = fmaf(a1.z, a1.z, n);
    n = fmaf(a1.w, a1.w, n);
    return n;
}

// ---- packed weight tables: built on device, then copied into __constant__ ----
struct __align__(16) CTab {
    ulonglong2 W1[32];   // (w0,w0 | w1,w1)
    ulonglong2 BW[32];   // (b1,b1 | 0.5*w2c,0.5*w2c)
    ulonglong2 W2[32];   // (0.5*w2a,.. | 0.5*w2b,..)
    U64        B2[3];    // (b2k, b2k)
    float      scal[2];  // lam, 1-lam
};

__device__   CTab dScratch;   // written by prep kernel
__constant__ CTab cT;         // read by main kernel (constant port)

__global__ void prep_kernel(const float* __restrict__ W1,
                            const float* __restrict__ b1,
                            const float* __restrict__ W2,
                            const float* __restrict__ b2,
                            const float* __restrict__ alpha)
{
    const int t = threadIdx.x;     // 32 threads
    float w0 = W1[2 * t], w1 = W1[2 * t + 1];
    ulonglong2 q; q.x = pk2(w0, w0); q.y = pk2(w1, w1);
    dScratch.W1[t] = q;
    float bb = b1[t], wc = 0.5f * W2[64 + t];
    ulonglong2 qb; qb.x = pk2(bb, bb); qb.y = pk2(wc, wc);
    dScratch.BW[t] = qb;
    float wa = 0.5f * W2[t], wb = 0.5f * W2[32 + t];
    ulonglong2 q2; q2.x = pk2(wa, wa); q2.y = pk2(wb, wb);
    dScratch.W2[t] = q2;
    if (t == 0) {
        float al  = alpha[0];
        float lam = 1.0f / (1.0f + __expf(-al));
        dScratch.scal[0] = lam;
        dScratch.scal[1] = 1.0f - lam;
        dScratch.B2[0] = pk2(b2[0], b2[0]);
        dScratch.B2[1] = pk2(b2[1], b2[1]);
        dScratch.B2[2] = pk2(b2[2], b2[2]);
    }
}

#define TPB 128          // threads per block
#define OPB 512          // octonions per block (4 per thread)

__global__ __launch_bounds__(TPB, 9)
void g2ff_kernel(const float4* __restrict__ in4,
                 float4*       __restrict__ out4)
{
    const int t = threadIdx.x;
    const int base = blockIdx.x * OPB;
    const int mA = base + t;
    const int mB = base + TPB + t;
    const int mC = base + 2 * TPB + t;
    const int mD = base + 3 * TPB + t;

    // ---- prologue: scalar n^2 per octonion; pack only (r, np) pairs ----
    U64 Xp0, Xnp, Yp0, Ynp;
    {
        float4 a0 = in4[2 * mA + 0];
        float4 a1 = in4[2 * mA + 1];
        float4 b0 = in4[2 * mB + 0];
        float4 b1v = in4[2 * mB + 1];
        float nA = norm2_imag(a0, a1);
        float nB = norm2_imag(b0, b1v);
        Xp0 = pk2(a0.x, b0.x);
        Xnp = pk2(sqrt_ap(nA), sqrt_ap(nB));
    }
    {
        float4 a0 = in4[2 * mC + 0];
        float4 a1 = in4[2 * mC + 1];
        float4 b0 = in4[2 * mD + 0];
        float4 b1v = in4[2 * mD + 1];
        float nA = norm2_imag(a0, a1);
        float nB = norm2_imag(b0, b1v);
        Yp0 = pk2(a0.x, b0.x);
        Ynp = pk2(sqrt_ap(nA), sqrt_ap(nB));
    }

    // GELU-tanh constants
    const U64 C1 = pk2(0.7978845608028654f, 0.7978845608028654f);
    const U64 C2 = pk2(0.035677408136300125f, 0.035677408136300125f);

    U64 aAX = cT.B2[0], aBX = cT.B2[1], aCX = cT.B2[2];
    U64 aAY = cT.B2[0], aBY = cT.B2[1], aCY = cT.B2[2];

#pragma unroll
    for (int j = 0; j < 32; j++) {
        ulonglong2 w1j = cT.W1[j];   // LDC.128 (constant port, off L1tex)
        ulonglong2 bwj = cT.BW[j];
        ulonglong2 w2j = cT.W2[j];

        // stream X:  h' = z*(1+tanh(u)) = 2*gelu(z); W2 tables pre-halved
        {
            U64 z  = fma2(Xnp, w1j.y, fma2(Xp0, w1j.x, bwj.x));
            U64 z2 = mul2(z, z);
            U64 qq = fma2(z2, C2, C1);
            U64 u  = mul2(z, qq);
            float ul, uh; upk2(u, ul, uh);
            U64 tt = pk2(tanh_ap(ul), tanh_ap(uh));
            U64 h  = fma2(z, tt, z);
            aAX = fma2(h, w2j.x, aAX);
            aBX = fma2(h, w2j.y, aBX);
            aCX = fma2(h, bwj.y, aCX);
        }
        // stream Y
        {
            U64 z  = fma2(Ynp, w1j.y, fma2(Yp0, w1j.x, bwj.x));
            U64 z2 = mul2(z, z);
            U64 qq = fma2(z2, C2, C1);
            U64 u  = mul2(z, qq);
            float ul, uh; upk2(u, ul, uh);
            U64 tt = pk2(tanh_ap(ul), tanh_ap(uh));
            U64 h  = fma2(z, tt, z);
            aAY = fma2(h, w2j.x, aAY);
            aBY = fma2(h, w2j.y, aBY);
            aCY = fma2(h, bwj.y, aCY);
        }
    }

    const U64 N1  = pk2(-1.0f, -1.0f);
    const U64 N3  = pk2(-3.0f, -3.0f);
    const U64 TWO = pk2(2.0f, 2.0f);

    const float lam = cT.scal[0], oml = cT.scal[1];
    const U64 LAM = pk2(lam, lam);
    const U64 OML = pk2(oml, oml);

    // ---- epilogue stream X (re-load octonions from global; L2 hit) ----
    {
        U64 n2 = mul2(Xnp, Xnp);              // recompute (np = sqrt(n2))
        U64 r2 = mul2(Xp0, Xp0);
        U64 s2 = fma2(n2, N1, r2);            // r^2 - n^2
        U64 u3 = fma2(n2, N3, r2);            // r^2 - 3n^2
        U64 s3 = mul2(Xp0, u3);
        U64 t3 = fma2(r2, TWO, s2);           // 3r^2 - n^2
        U64 P  = fma2(aAX, Xp0, fma2(aBX, s2, mul2(aCX, s3)));
        U64 tr = add2(Xp0, Xp0);
        U64 Q  = fma2(aCX, t3, fma2(aBX, tr, aAX));
        U64 ss = fma2(mul2(Q, Q), n2, mul2(P, P));
        float sl, sh; upk2(ss, sl, sh);
        sl = fmaxf(sl, 1e-16f);
        sh = fmaxf(sh, 1e-16f);
        U64 inv = pk2(rsqrt_ap(sl), rsqrt_ap(sh));
        U64 li  = mul2(LAM, inv);
        U64 K   = fma2(li, Q, OML);
        U64 o0  = fma2(li, P, mul2(Xp0, OML));

        float Klo, Khi; upk2(K, Klo, Khi);
        float olo, ohi; upk2(o0, olo, ohi);

        float4 a0 = in4[2 * mA + 0];
        float4 a1 = in4[2 * mA + 1];
        a0.x = olo;
        a0.y *= Klo; a0.z *= Klo; a0.w *= Klo;
        a1.x *= Klo; a1.y *= Klo; a1.z *= Klo; a1.w *= Klo;
        out4[2 * mA + 0] = a0;
        out4[2 * mA + 1] = a1;

        float4 b0 = in4[2 * mB + 0];
        float4 b1v = in4[2 * mB + 1];
        b0.x = ohi;
        b0.y *= Khi; b0.z *= Khi; b0.w *= Khi;
        b1v.x *= Khi; b1v.y *= Khi; b1v.z *= Khi; b1v.w *= Khi;
        out4[2 * mB + 0] = b0;
        out4[2 * mB + 1] = b1v;
    }
    // ---- epilogue stream Y ----
    {
        U64 n2 = mul2(Ynp, Ynp);
        U64 r2 = mul2(Yp0, Yp0);
        U64 s2 = fma2(n2, N1, r2);
        U64 u3 = fma2(n2, N3, r2);
        U64 s3 = mul2(Yp0, u3);
        U64 t3 = fma2(r2, TWO, s2);
        U64 P  = fma2(aAY, Yp0, fma2(aBY, s2, mul2(aCY, s3)));
        U64 tr = add2(Yp0, Yp0);
        U64 Q  = fma2(aCY, t3, fma2(aBY, tr, aAY));
        U64 ss = fma2(mul2(Q, Q), n2, mul2(P, P));
        float sl, sh; upk2(ss, sl, sh);
        sl = fmaxf(sl, 1e-16f);
        sh = fmaxf(sh, 1e-16f);
        U64 inv = pk2(rsqrt_ap(sl), rsqrt_ap(sh));
        U64 li  = mul2(LAM, inv);
        U64 K   = fma2(li, Q, OML);
        U64 o0  = fma2(li, P, mul2(Yp0, OML));

        float Klo, Khi; upk2(K, Klo, Khi);
        float olo, ohi; upk2(o0, olo, ohi);

        float4 a0 = in4[2 * mC + 0];
        float4 a1 = in4[2 * mC + 1];
        a0.x = olo;
        a0.y *= Klo; a0.z *= Klo; a0.w *= Klo;
        a1.x *= Klo; a1.y *= Klo; a1.z *= Klo; a1.w *= Klo;
        out4[2 * mC + 0] = a0;
        out4[2 * mC + 1] = a1;

        float4 b0 = in4[2 * mD + 0];
        float4 b1v = in4[2 * mD + 1];
        b0.x = ohi;
        b0.y *= Khi; b0.z *= Khi; b0.w *= Khi;
        b1v.x *= Khi; b1v.y *= Khi; b1v.z *= Khi; b1v.w *= Khi;
        out4[2 * mD + 0] = b0;
        out4[2 * mD + 1] = b1v;
    }
}

extern "C" void kernel_launch(void* const* d_in, const int* in_sizes, int n_in,
                              void* d_out, int out_size)
{
    const float* o     = (const float*)d_in[0];
    const float* W1    = (const float*)d_in[1];
    const float* b1    = (const float*)d_in[2];
    const float* W2    = (const float*)d_in[3];
    const float* b2    = (const float*)d_in[4];
    const float* alpha = (const float*)d_in[5];

    // 1) pack weight tables on device
    prep_kernel<<<1, 32>>>(W1, b1, W2, b2, alpha);

    // 2) copy packed tables into __constant__ (D2D memcpy node, capturable)
    void* scratch_addr = nullptr;
    cudaGetSymbolAddress(&scratch_addr, dScratch);
    cudaMemcpyToSymbolAsync(cT, scratch_addr, sizeof(CTab), 0,
                            cudaMemcpyDeviceToDevice);

    // 3) main kernel
    const int total = in_sizes[0];          // 33,554,432 floats
    const int octs  = total / 8;            // 4,194,304 octonions
    const int blocks = octs / OPB;          // 8192

    g2ff_kernel<<<blocks, TPB>>>((const float4*)o, (float4*)d_out);
}